// round 6
// baseline (speedup 1.0000x reference)
#include <cuda_runtime.h>

// Problem constants
static const int BB  = 8;
static const int NN  = 20000;
static const int DD  = 64;
static const int DD2 = 128;
static const int RR  = 24;
static const int SS  = 3;
static const int EE  = 60000;
static const int KK  = 101;
static const int HL  = 50;
static const int FDIM = 192;   // D + 2D
static const int ECAP = 512;   // per-block staged edge capacity (mean 48, Poisson tail << 512)

// packed fp32x2 helpers (SASS FFMA2 path)
#define FMA_F32X2(d, a, b, c) \
    asm("fma.rn.f32x2 %0, %1, %2, %3;" : "=l"(d) : "l"(a), "l"(b), "l"(c))
#define PACKF2(d, lo, hi) \
    asm("mov.b64 %0, {%1, %2};" : "=l"(d) : "f"(lo), "f"(hi))
#define UNPACKF2(lo, hi, v) \
    asm("mov.b64 {%0, %1}, %2;" : "=f"(lo), "=f"(hi) : "l"(v))

// ---------------- scratch (device globals; no allocations allowed) ----------
__device__ float g_init[BB * NN * DD];
__device__ float g_xA[BB * NN * DD];
__device__ float g_xB[BB * NN * DD];
__device__ int   g_cnt_poi[SS][NN];
__device__ int   g_cnt_dst[SS][NN];
__device__ int   g_rowstart[SS][NN];
__device__ int   g_rowfill[SS][NN];
__device__ int   g_total[SS];
__device__ int   g_csr_src[SS][EE];
__device__ int   g_csr_et[SS][EE];
__device__ float g_relsum[SS][2][NN * DD];
__device__ float g_query[BB * DD];
__device__ float g_xseq[BB * HL * DD2];
__device__ float g_qkv[BB * HL * 3 * DD2];
__device__ float g_ao[BB * HL * DD2];
__device__ float g_h1[BB * HL * 4 * DD2];
__device__ float g_flabel[BB * DD2];

// ---------------- CSR build (batched over all S snapshots) -------------------
__global__ void k_zero_counts() {
    int s = blockIdx.y;
    int i = blockIdx.x * blockDim.x + threadIdx.x;
    if (i < NN) { g_cnt_poi[s][i] = 0; g_cnt_dst[s][i] = 0; g_rowfill[s][i] = 0; }
    if (i == 0) g_total[s] = 0;
}

__global__ void k_count(const int* __restrict__ src, const int* __restrict__ dst) {
    int s = blockIdx.y;
    int e = blockIdx.x * blockDim.x + threadIdx.x;
    if (e < EE) {
        atomicAdd(&g_cnt_poi[s][src[s * EE + e]], 1);
        atomicAdd(&g_cnt_poi[s][dst[s * EE + e]], 1);
        atomicAdd(&g_cnt_dst[s][dst[s * EE + e]], 1);
    }
}

// warp-aggregated contiguous range assignment (order-free)
__global__ void k_offsets() {
    int s = blockIdx.y;
    int n = blockIdx.x * blockDim.x + threadIdx.x;
    int lane = threadIdx.x & 31;
    int c = (n < NN) ? g_cnt_dst[s][n] : 0;
    int pre = c;
    #pragma unroll
    for (int off = 1; off < 32; off <<= 1) {
        int t = __shfl_up_sync(0xffffffffu, pre, off);
        if (lane >= off) pre += t;
    }
    int tot = __shfl_sync(0xffffffffu, pre, 31);
    int base = 0;
    if (lane == 31 && tot > 0) base = atomicAdd(&g_total[s], tot);
    base = __shfl_sync(0xffffffffu, base, 31);
    if (n < NN) g_rowstart[s][n] = base + pre - c;
}

__global__ void k_scatter(const int* __restrict__ src, const int* __restrict__ dst,
                          const int* __restrict__ et) {
    int s = blockIdx.y;
    int e = blockIdx.x * blockDim.x + threadIdx.x;
    if (e < EE) {
        int dn = dst[s * EE + e];
        int pos = g_rowstart[s][dn] + atomicAdd(&g_rowfill[s][dn], 1);
        g_csr_src[s][pos] = src[s * EE + e];
        g_csr_et[s][pos]  = et[s * EE + e];
    }
}

// per-node, per-layer sum of relation embeddings (batch-independent), all s
__global__ void k_relsum(const float* __restrict__ rel) {  // rel: [2, R, D]
    int s = blockIdx.y;
    int i = blockIdx.x * blockDim.x + threadIdx.x;  // NN*DD
    if (i >= NN * DD) return;
    int n = i >> 6, j = i & 63;
    int rs = g_rowstart[s][n], cnt = g_cnt_dst[s][n];
    float a0 = 0.f, a1 = 0.f;
    for (int p = rs; p < rs + cnt; p++) {
        int r = __ldg(&g_csr_et[s][p]);
        a0 += __ldg(&rel[r * DD + j]);
        a1 += __ldg(&rel[RR * DD + r * DD + j]);
    }
    g_relsum[s][0][i] = a0;
    g_relsum[s][1][i] = a1;
}

// ---------------- init (snapshot 0: single batch row) ------------------------
__global__ void k_init0(const float* __restrict__ poi) {
    int i = blockIdx.x * blockDim.x + threadIdx.x;
    if (i < NN * DD) {
        int n = i >> 6;
        g_init[i] = (float)g_cnt_poi[0][n] * poi[i];
    }
}

// 16 rows per block, 256 threads. prev output in g_xB; prevBS = 0 (b0 bcast) or NN*DD.
__global__ void k_gate_init(const float* __restrict__ poi,
                            const float* __restrict__ gW,
                            const float* __restrict__ gb, int prevBS, int s) {
    const int P = 20;
    __shared__ float s_in[DD * P];
    int n0 = blockIdx.x * 16;
    int b  = blockIdx.y;
    int tid = threadIdx.x;
    int j   = tid & 63;
    int gbk = tid >> 6;
    #pragma unroll
    for (int gi = 0; gi < 4; gi++) {
        int g = gbk * 4 + gi;
        int n = n0 + g;
        s_in[j * P + g] = g_xB[b * prevBS + n * DD + j];
    }
    __syncthreads();
    float bj = gb[j];
    unsigned long long acc01, acc23;
    PACKF2(acc01, bj, bj);
    acc23 = acc01;
    #pragma unroll 8
    for (int k = 0; k < DD; k++) {
        float w = __ldg(&gW[k * DD + j]);
        unsigned long long wd;
        PACKF2(wd, w, w);
        ulonglong2 x = *reinterpret_cast<const ulonglong2*>(&s_in[k * P + gbk * 4]);
        FMA_F32X2(acc01, wd, x.x, acc01);
        FMA_F32X2(acc23, wd, x.y, acc23);
    }
    float accs[4];
    UNPACKF2(accs[0], accs[1], acc01);
    UNPACKF2(accs[2], accs[3], acc23);
    #pragma unroll
    for (int gi = 0; gi < 4; gi++) {
        int g = gbk * 4 + gi;
        int n = n0 + g;
        float gt = 1.f / (1.f + __expf(-accs[gi]));
        float prv = s_in[j * P + g];
        float ione = (float)g_cnt_poi[s][n] * poi[n * DD + j];
        g_init[(b * NN + n) * DD + j] = ione * gt + (1.f - gt) * prv;
    }
}

// ---------------- fused GNN layer: edge-parallel gather + GEMM + ReLU --------
__global__ void k_layer(int s, int layer,
                        const float* __restrict__ W,
                        const float* __restrict__ bias) {
    const int P = 20;
    __shared__ float s_in[2 * DD * P];   // [cols 0..63]=agg, [64..127]=init; node-minor
    __shared__ int   s_edge[ECAP];       // packed src*16 + localDst
    __shared__ int   s_ne;
    int n0 = blockIdx.x * 16;
    int b  = blockIdx.y;
    int tid = threadIdx.x;
    int j   = tid & 63;
    int gbk = tid >> 6;
    const float* xin  = (layer == 0) ? g_init : g_xA;
    float*       xout = (layer == 0) ? g_xA : g_xB;
    const float* relsum = g_relsum[s][layer];
    const float* xb = xin + b * NN * DD;

    // ---- stage edge list (lanes 0..15 of warp 0) ----
    if (tid < 16) {
        int n = n0 + tid;
        int cnt = g_cnt_dst[s][n];
        int pre = cnt;
        #pragma unroll
        for (int off = 1; off < 16; off <<= 1) {
            int t = __shfl_up_sync(0x0000ffffu, pre, off);
            if (tid >= off) pre += t;
        }
        int base = pre - cnt;
        if (tid == 15) s_ne = (pre < ECAP) ? pre : ECAP;
        int rs = g_rowstart[s][n];
        for (int q = 0; q < cnt; q++) {
            int pos = base + q;
            if (pos < ECAP) s_edge[pos] = __ldg(&g_csr_src[s][rs + q]) * 16 + tid;
        }
    }
    // ---- seed accumulators with relsum; load init half ----
    #pragma unroll
    for (int gi = 0; gi < 4; gi++) {
        int g = gbk * 4 + gi;
        int n = n0 + g;
        s_in[j * P + g] = __ldg(&relsum[n * DD + j]);
        s_in[(DD + j) * P + g] = g_init[(b * NN + n) * DD + j];
    }
    __syncthreads();

    // ---- edge-parallel gather: flat (edge, col) items, high MLP ----
    int ne = s_ne;
    int items = ne * 64;
    for (int idx = tid; idx < items; idx += 256) {
        int e = idx >> 6, j2 = idx & 63;
        int pk = s_edge[e];
        int src = pk >> 4, le = pk & 15;
        float v = __ldg(&xb[src * DD + j2]);
        atomicAdd(&s_in[j2 * P + le], v);
    }
    __syncthreads();

    // ---- GEMM: [agg|init] @ W + bias, f32x2 ----
    float bj = bias[j];
    unsigned long long acc01, acc23;
    PACKF2(acc01, bj, bj);
    acc23 = acc01;
    #pragma unroll 8
    for (int k = 0; k < 2 * DD; k++) {
        float w = __ldg(&W[k * DD + j]);
        unsigned long long wd;
        PACKF2(wd, w, w);
        ulonglong2 x = *reinterpret_cast<const ulonglong2*>(&s_in[k * P + gbk * 4]);
        FMA_F32X2(acc01, wd, x.x, acc01);
        FMA_F32X2(acc23, wd, x.y, acc23);
    }
    float accs[4];
    UNPACKF2(accs[0], accs[1], acc01);
    UNPACKF2(accs[2], accs[3], acc23);
    #pragma unroll
    for (int gi = 0; gi < 4; gi++) {
        int n = n0 + gbk * 4 + gi;
        xout[(b * NN + n) * DD + j] = fmaxf(accs[gi], 0.f);
    }
}

// ---------------- query handling ---------------------------------------------
__global__ void k_qinit(const float* __restrict__ qe, const int* __restrict__ ridx) {
    int tid = threadIdx.x;           // 512 = B*D
    int b = tid >> 6, d = tid & 63;
    g_query[tid] = qe[ridx[b] * DD + d];
}

__global__ void k_qupd(const float* __restrict__ temb, const int* __restrict__ gtime,
                       int s, const float* __restrict__ lw, const float* __restrict__ lb) {
    __shared__ float sq[BB * DD];
    int tid = threadIdx.x;           // 512
    int b = tid >> 6, d = tid & 63;
    int t = gtime[s];
    sq[tid] = g_query[tid] + temb[t * DD + d];
    __syncthreads();
    float acc = lb[d];
    #pragma unroll 8
    for (int k = 0; k < DD; k++) acc = fmaf(sq[b * DD + k], lw[k * DD + d], acc);
    g_query[tid] = acc;
}

// ---------------- sequence build + transformer -------------------------------
__global__ void k_xseq(const int* __restrict__ hp, const float* __restrict__ hte) {
    int row = blockIdx.x;            // 0..B*HL-1
    int b = row / HL;
    int j = threadIdx.x;             // 128
    int p = hp[row];
    float v = (j < DD) ? g_xB[(b * NN + p) * DD + j] : g_query[b * DD + (j - DD)];
    g_xseq[row * DD2 + j] = v + hte[row * DD2 + j];
}

__global__ void k_qkv(const float* __restrict__ Wqkv, int l) {
    __shared__ float sx[DD2];
    int row = blockIdx.x;
    int c = threadIdx.x;             // 384
    if (c < DD2) sx[c] = g_xseq[row * DD2 + c];
    __syncthreads();
    const float* W = Wqkv + l * DD2 * 3 * DD2;
    float acc = 0.f;
    #pragma unroll 8
    for (int k = 0; k < DD2; k++) acc = fmaf(sx[k], __ldg(&W[k * 384 + c]), acc);
    g_qkv[row * 384 + c] = acc;
}

__global__ void k_att() {
    const int PQ = 65;
    __shared__ float sq[HL * PQ];
    __shared__ float sk[HL * PQ];
    __shared__ float sv[HL * PQ];
    __shared__ float ss[HL * HL];
    int b = blockIdx.x, h = blockIdx.y;
    int tid = threadIdx.x;           // 256
    for (int i = tid; i < HL * DD; i += 256) {
        int t = i / DD, d = i & 63;
        int base = (b * HL + t) * 384 + h * 64 + d;
        sq[t * PQ + d] = g_qkv[base];
        sk[t * PQ + d] = g_qkv[base + 128];
        sv[t * PQ + d] = g_qkv[base + 256];
    }
    __syncthreads();
    for (int o = tid; o < HL * HL; o += 256) {
        int i = o / HL, jj = o % HL;
        float acc = 0.f;
        #pragma unroll 8
        for (int d = 0; d < 64; d++) acc = fmaf(sq[i * PQ + d], sk[jj * PQ + d], acc);
        ss[o] = acc * 0.125f;
    }
    __syncthreads();
    for (int i = tid; i < HL; i += 256) {
        float m = -1e30f;
        for (int jj = 0; jj < HL; jj++) m = fmaxf(m, ss[i * HL + jj]);
        float sum = 0.f;
        for (int jj = 0; jj < HL; jj++) { float e = __expf(ss[i * HL + jj] - m); ss[i * HL + jj] = e; sum += e; }
        float inv = 1.f / sum;
        for (int jj = 0; jj < HL; jj++) ss[i * HL + jj] *= inv;
    }
    __syncthreads();
    for (int o = tid; o < HL * DD; o += 256) {
        int i = o / DD, d = o & 63;
        float acc = 0.f;
        #pragma unroll 5
        for (int jj = 0; jj < HL; jj++) acc = fmaf(ss[i * HL + jj], sv[jj * PQ + d], acc);
        g_ao[(b * HL + i) * DD2 + h * 64 + d] = acc;
    }
}

__global__ void k_proj_ln(const float* __restrict__ Wo, const float* __restrict__ ln1, int l) {
    __shared__ float so[DD2];
    __shared__ float red[DD2];
    int row = blockIdx.x;
    int j = threadIdx.x;             // 128
    so[j] = g_ao[row * DD2 + j];
    __syncthreads();
    const float* W = Wo + l * DD2 * DD2;
    float acc = 0.f;
    #pragma unroll 8
    for (int k = 0; k < DD2; k++) acc = fmaf(so[k], __ldg(&W[k * DD2 + j]), acc);
    float v = g_xseq[row * DD2 + j] + acc;
    red[j] = v;
    __syncthreads();
    for (int off = 64; off > 0; off >>= 1) { if (j < off) red[j] += red[j + off]; __syncthreads(); }
    float mean = red[0] * (1.f / 128.f);
    __syncthreads();
    float dv = v - mean;
    red[j] = dv * dv;
    __syncthreads();
    for (int off = 64; off > 0; off >>= 1) { if (j < off) red[j] += red[j + off]; __syncthreads(); }
    float var = red[0] * (1.f / 128.f);
    const float* lnl = ln1 + l * 2 * DD2;
    g_xseq[row * DD2 + j] = dv * rsqrtf(var + 1e-5f) * lnl[j] + lnl[DD2 + j];
}

__global__ void k_ff1(const float* __restrict__ W1, const float* __restrict__ b1, int l) {
    __shared__ float sx[DD2];
    int row = blockIdx.x;
    int c = threadIdx.x;             // 512
    if (c < DD2) sx[c] = g_xseq[row * DD2 + c];
    __syncthreads();
    const float* W = W1 + l * DD2 * 512;
    float acc = b1[l * 512 + c];
    #pragma unroll 8
    for (int k = 0; k < DD2; k++) acc = fmaf(sx[k], __ldg(&W[k * 512 + c]), acc);
    g_h1[row * 512 + c] = fmaxf(acc, 0.f);
}

__global__ void k_ff2_ln(const float* __restrict__ W2, const float* __restrict__ b2,
                         const float* __restrict__ ln2, int l) {
    __shared__ float sh[512];
    __shared__ float red[DD2];
    int row = blockIdx.x;
    int j = threadIdx.x;             // 128
    for (int k = j; k < 512; k += 128) sh[k] = g_h1[row * 512 + k];
    __syncthreads();
    const float* W = W2 + l * 512 * DD2;
    float acc = b2[l * DD2 + j];
    #pragma unroll 8
    for (int k = 0; k < 512; k++) acc = fmaf(sh[k], __ldg(&W[k * DD2 + j]), acc);
    float v = g_xseq[row * DD2 + j] + acc;
    red[j] = v;
    __syncthreads();
    for (int off = 64; off > 0; off >>= 1) { if (j < off) red[j] += red[j + off]; __syncthreads(); }
    float mean = red[0] * (1.f / 128.f);
    __syncthreads();
    float dv = v - mean;
    red[j] = dv * dv;
    __syncthreads();
    for (int off = 64; off > 0; off >>= 1) { if (j < off) red[j] += red[j + off]; __syncthreads(); }
    float var = red[0] * (1.f / 128.f);
    const float* lnl = ln2 + l * 2 * DD2;
    g_xseq[row * DD2 + j] = dv * rsqrtf(var + 1e-5f) * lnl[j] + lnl[DD2 + j];
}

__global__ void k_flabel() {
    int b = blockIdx.x;
    int j = threadIdx.x;             // 128
    float s = 0.f;
    for (int t = 0; t < HL; t++) s += g_xseq[(b * HL + t) * DD2 + j];
    g_flabel[b * DD2 + j] = s * (1.f / (float)HL);
}

// ---------------- final scoring MLP -------------------------------------------
__global__ void k_score(const int* __restrict__ tidx,
                        const float* __restrict__ W1, const float* __restrict__ b1,
                        const float* __restrict__ W2, const float* __restrict__ b2,
                        float* __restrict__ out) {
    __shared__ float ft[FDIM];
    __shared__ float sh[256];
    int blk = blockIdx.x;
    int b = blk / KK;
    int j = threadIdx.x;             // 192
    int ti = tidx[blk];
    ft[j] = (j < DD) ? g_xB[(b * NN + ti) * DD + j] : g_flabel[b * DD2 + (j - DD)];
    if (j < 64) sh[192 + j] = 0.f;
    __syncthreads();
    float acc = b1[j];
    #pragma unroll 8
    for (int q = 0; q < FDIM; q++) acc = fmaf(ft[q], __ldg(&W1[q * FDIM + j]), acc);
    float h = fmaxf(acc, 0.f);
    sh[j] = h * W2[j];
    __syncthreads();
    for (int off = 128; off > 0; off >>= 1) { if (j < off) sh[j] += sh[j + off]; __syncthreads(); }
    if (j == 0) out[blk] = sh[0] + b2[0];
}

// ---------------- host launcher -------------------------------------------------
extern "C" void kernel_launch(void* const* d_in, const int* in_sizes, int n_in,
                              void* d_out, int out_size) {
    const float* poi   = (const float*)d_in[0];
    const float* qemb  = (const float*)d_in[1];
    const float* gateW = (const float*)d_in[2];
    const float* gateb = (const float*)d_in[3];
    const float* gnn_rel = (const float*)d_in[4];
    const float* gnn_W   = (const float*)d_in[5];
    const float* gnn_b   = (const float*)d_in[6];
    const float* gte  = (const float*)d_in[7];
    const float* glW  = (const float*)d_in[8];
    const float* glb  = (const float*)d_in[9];
    const float* Wqkv = (const float*)d_in[10];
    const float* Wo   = (const float*)d_in[11];
    const float* ln1  = (const float*)d_in[12];
    const float *W1, *b1, *W2, *b2, *ln2;
    if (in_sizes[13] == 2 * 2 * DD2) {       // dict order: ln2 right after ln1
        ln2 = (const float*)d_in[13];
        W1  = (const float*)d_in[14];
        b1  = (const float*)d_in[15];
        W2  = (const float*)d_in[16];
        b2  = (const float*)d_in[17];
    } else {                                 // signature order
        W1  = (const float*)d_in[13];
        b1  = (const float*)d_in[14];
        W2  = (const float*)d_in[15];
        b2  = (const float*)d_in[16];
        ln2 = (const float*)d_in[17];
    }
    const float* mW1 = (const float*)d_in[18];
    const float* mb1 = (const float*)d_in[19];
    const float* mW2 = (const float*)d_in[20];
    const float* mb2 = (const float*)d_in[21];
    const float* hte = (const float*)d_in[22];
    const int* esrc  = (const int*)d_in[23];
    const int* edst  = (const int*)d_in[24];
    const int* etyp  = (const int*)d_in[25];
    const int* ridx  = (const int*)d_in[27];
    const int* tidx  = (const int*)d_in[28];
    const int* hpoi  = (const int*)d_in[29];
    const int* gtime = (const int*)d_in[30];
    float* out = (float*)d_out;

    k_qinit<<<1, BB * DD>>>(qemb, ridx);

    // batched CSR for all snapshots
    k_zero_counts<<<dim3((NN + 255) / 256, SS), 256>>>();
    k_count<<<dim3((EE + 255) / 256, SS), 256>>>(esrc, edst);
    k_offsets<<<dim3((NN + 255) / 256, SS), 256>>>();
    k_scatter<<<dim3((EE + 255) / 256, SS), 256>>>(esrc, edst, etyp);
    k_relsum<<<dim3(NN * DD / 256, SS), 256>>>(gnn_rel);

    for (int s = 0; s < SS; s++) {
        int nb = (s == 0) ? 1 : BB;          // snapshot 0 is batch-invariant
        if (s == 0)
            k_init0<<<(NN * DD + 255) / 256, 256>>>(poi);
        else
            k_gate_init<<<dim3(NN / 16, BB), 256>>>(poi, gateW, gateb,
                                                    (s == 1) ? 0 : NN * DD, s);
        for (int l = 0; l < 2; l++) {
            k_layer<<<dim3(NN / 16, nb), 256>>>(s, l,
                                                gnn_W + l * 2 * DD * DD,
                                                gnn_b + l * DD);
        }
        k_qupd<<<1, BB * DD>>>(gte, gtime, s, glW, glb);
    }

    k_xseq<<<BB * HL, DD2>>>(hpoi, hte);
    for (int l = 0; l < 2; l++) {
        k_qkv<<<BB * HL, 3 * DD2>>>(Wqkv, l);
        k_att<<<dim3(BB, 2), 256>>>();
        k_proj_ln<<<BB * HL, DD2>>>(Wo, ln1, l);
        k_ff1<<<BB * HL, 4 * DD2>>>(W1, b1, l);
        k_ff2_ln<<<BB * HL, DD2>>>(W2, b2, ln2, l);
    }
    k_flabel<<<BB, DD2>>>();
    k_score<<<BB * KK, FDIM>>>(tidx, mW1, mb1, mW2, mb2, out);
}

// round 7
// speedup vs baseline: 1.1382x; 1.1382x over previous
#include <cuda_runtime.h>

// Problem constants
static const int BB  = 8;
static const int NN  = 20000;
static const int DD  = 64;
static const int DD2 = 128;
static const int RR  = 24;
static const int SS  = 3;
static const int EE  = 60000;
static const int KK  = 101;
static const int HL  = 50;
static const int FDIM = 192;   // D + 2D

// packed fp32x2 helpers (SASS FFMA2 path)
#define FMA_F32X2(d, a, b, c) \
    asm("fma.rn.f32x2 %0, %1, %2, %3;" : "=l"(d) : "l"(a), "l"(b), "l"(c))
#define PACKF2(d, lo, hi) \
    asm("mov.b64 %0, {%1, %2};" : "=l"(d) : "f"(lo), "f"(hi))
#define UNPACKF2(lo, hi, v) \
    asm("mov.b64 {%0, %1}, %2;" : "=f"(lo), "=f"(hi) : "l"(v))

// ---------------- scratch (device globals; no allocations allowed) ----------
__device__ float g_init[BB * NN * DD];
__device__ float g_xA[BB * NN * DD];
__device__ float g_xB[BB * NN * DD];
__device__ int   g_cnt_poi[SS][NN];
__device__ int   g_cnt_dst[SS][NN];
__device__ int   g_rowstart[SS][NN];
__device__ int   g_rowfill[SS][NN];
__device__ int   g_total[SS];
__device__ int   g_csr_src[SS][EE];
__device__ int   g_csr_et[SS][EE];
__device__ float g_relsum[SS][2][NN * DD];
__device__ float g_query[BB * DD];
__device__ float g_xseq[BB * HL * DD2];
__device__ float g_qkv[BB * HL * 3 * DD2];
__device__ float g_ao[BB * HL * DD2];
__device__ float g_flabel[BB * DD2];

// ---------------- CSR build (batched over all S snapshots) -------------------
__global__ void k_zero_counts() {
    int s = blockIdx.y;
    int i = blockIdx.x * blockDim.x + threadIdx.x;
    if (i < NN) { g_cnt_poi[s][i] = 0; g_cnt_dst[s][i] = 0; g_rowfill[s][i] = 0; }
    if (i == 0) g_total[s] = 0;
}

__global__ void k_count(const int* __restrict__ src, const int* __restrict__ dst) {
    int s = blockIdx.y;
    int e = blockIdx.x * blockDim.x + threadIdx.x;
    if (e < EE) {
        atomicAdd(&g_cnt_poi[s][src[s * EE + e]], 1);
        atomicAdd(&g_cnt_poi[s][dst[s * EE + e]], 1);
        atomicAdd(&g_cnt_dst[s][dst[s * EE + e]], 1);
    }
}

// warp-aggregated contiguous range assignment (order-free)
__global__ void k_offsets() {
    int s = blockIdx.y;
    int n = blockIdx.x * blockDim.x + threadIdx.x;
    int lane = threadIdx.x & 31;
    int c = (n < NN) ? g_cnt_dst[s][n] : 0;
    int pre = c;
    #pragma unroll
    for (int off = 1; off < 32; off <<= 1) {
        int t = __shfl_up_sync(0xffffffffu, pre, off);
        if (lane >= off) pre += t;
    }
    int tot = __shfl_sync(0xffffffffu, pre, 31);
    int base = 0;
    if (lane == 31 && tot > 0) base = atomicAdd(&g_total[s], tot);
    base = __shfl_sync(0xffffffffu, base, 31);
    if (n < NN) g_rowstart[s][n] = base + pre - c;
}

__global__ void k_scatter(const int* __restrict__ src, const int* __restrict__ dst,
                          const int* __restrict__ et) {
    int s = blockIdx.y;
    int e = blockIdx.x * blockDim.x + threadIdx.x;
    if (e < EE) {
        int dn = dst[s * EE + e];
        int pos = g_rowstart[s][dn] + atomicAdd(&g_rowfill[s][dn], 1);
        g_csr_src[s][pos] = src[s * EE + e];
        g_csr_et[s][pos]  = et[s * EE + e];
    }
}

// per-node, per-layer sum of relation embeddings (batch-independent), all s
__global__ void k_relsum(const float* __restrict__ rel) {  // rel: [2, R, D]
    int s = blockIdx.y;
    int i = blockIdx.x * blockDim.x + threadIdx.x;  // NN*DD
    if (i >= NN * DD) return;
    int n = i >> 6, j = i & 63;
    int rs = g_rowstart[s][n], cnt = g_cnt_dst[s][n];
    float a0 = 0.f, a1 = 0.f;
    for (int p = rs; p < rs + cnt; p++) {
        int r = __ldg(&g_csr_et[s][p]);
        a0 += __ldg(&rel[r * DD + j]);
        a1 += __ldg(&rel[RR * DD + r * DD + j]);
    }
    g_relsum[s][0][i] = a0;
    g_relsum[s][1][i] = a1;
}

// ---------------- init (snapshot 0: single batch row) ------------------------
__global__ void k_init0(const float* __restrict__ poi) {
    int i = blockIdx.x * blockDim.x + threadIdx.x;
    if (i < NN * DD) {
        int n = i >> 6;
        g_init[i] = (float)g_cnt_poi[0][n] * poi[i];
    }
}

// 16 rows per block, 256 threads. prev output in g_xB; prevBS = 0 (b0 bcast) or NN*DD.
__global__ void k_gate_init(const float* __restrict__ poi,
                            const float* __restrict__ gW,
                            const float* __restrict__ gb, int prevBS, int s) {
    const int P = 20;
    __shared__ float s_in[DD * P];
    int n0 = blockIdx.x * 16;
    int b  = blockIdx.y;
    int tid = threadIdx.x;
    int j   = tid & 63;
    int gbk = tid >> 6;
    #pragma unroll
    for (int gi = 0; gi < 4; gi++) {
        int g = gbk * 4 + gi;
        int n = n0 + g;
        s_in[j * P + g] = g_xB[b * prevBS + n * DD + j];
    }
    __syncthreads();
    float bj = gb[j];
    unsigned long long acc01, acc23;
    PACKF2(acc01, bj, bj);
    acc23 = acc01;
    #pragma unroll 8
    for (int k = 0; k < DD; k++) {
        float w = __ldg(&gW[k * DD + j]);
        unsigned long long wd;
        PACKF2(wd, w, w);
        ulonglong2 x = *reinterpret_cast<const ulonglong2*>(&s_in[k * P + gbk * 4]);
        FMA_F32X2(acc01, wd, x.x, acc01);
        FMA_F32X2(acc23, wd, x.y, acc23);
    }
    float accs[4];
    UNPACKF2(accs[0], accs[1], acc01);
    UNPACKF2(accs[2], accs[3], acc23);
    #pragma unroll
    for (int gi = 0; gi < 4; gi++) {
        int g = gbk * 4 + gi;
        int n = n0 + g;
        float gt = 1.f / (1.f + __expf(-accs[gi]));
        float prv = s_in[j * P + g];
        float ione = (float)g_cnt_poi[s][n] * poi[n * DD + j];
        g_init[(b * NN + n) * DD + j] = ione * gt + (1.f - gt) * prv;
    }
}

// ---------------- fused GNN layer: gather + [agg|init] @ W + ReLU ------------
// 512 threads: 8 j-groups gather 2 nodes each (short chains); lower 256 do GEMM.
__global__ void k_layer(int s, int layer,
                        const float* __restrict__ W,
                        const float* __restrict__ bias) {
    const int P = 20;
    __shared__ float s_in[2 * DD * P];
    int n0 = blockIdx.x * 16;
    int b  = blockIdx.y;
    int tid = threadIdx.x;
    int j   = tid & 63;
    int grp = tid >> 6;              // 0..7
    const float* xin  = (layer == 0) ? g_init : g_xA;
    float*       xout = (layer == 0) ? g_xA : g_xB;
    const float* relsum = g_relsum[s][layer];
    const int* csr = g_csr_src[s];
    const float* xb = xin + b * NN * DD;
    #pragma unroll
    for (int gi = 0; gi < 2; gi++) {
        int g = grp * 2 + gi;
        int n = n0 + g;
        int rs = g_rowstart[s][n], cnt = g_cnt_dst[s][n];
        float acc = __ldg(&relsum[n * DD + j]);
        for (int p = rs; p < rs + cnt; p++)
            acc += xb[__ldg(&csr[p]) * DD + j];
        s_in[j * P + g] = acc;
        s_in[(DD + j) * P + g] = g_init[(b * NN + n) * DD + j];
    }
    __syncthreads();
    if (tid < 256) {
        int gbk = tid >> 6;          // 0..3
        float bj = bias[j];
        unsigned long long acc01, acc23;
        PACKF2(acc01, bj, bj);
        acc23 = acc01;
        #pragma unroll 8
        for (int k = 0; k < 2 * DD; k++) {
            float w = __ldg(&W[k * DD + j]);
            unsigned long long wd;
            PACKF2(wd, w, w);
            ulonglong2 x = *reinterpret_cast<const ulonglong2*>(&s_in[k * P + gbk * 4]);
            FMA_F32X2(acc01, wd, x.x, acc01);
            FMA_F32X2(acc23, wd, x.y, acc23);
        }
        float accs[4];
        UNPACKF2(accs[0], accs[1], acc01);
        UNPACKF2(accs[2], accs[3], acc23);
        #pragma unroll
        for (int gi = 0; gi < 4; gi++) {
            int n = n0 + gbk * 4 + gi;
            xout[(b * NN + n) * DD + j] = fmaxf(accs[gi], 0.f);
        }
    }
}

// ---------------- query handling ---------------------------------------------
__global__ void k_qinit(const float* __restrict__ qe, const int* __restrict__ ridx) {
    int tid = threadIdx.x;           // 512 = B*D
    int b = tid >> 6, d = tid & 63;
    g_query[tid] = qe[ridx[b] * DD + d];
}

__global__ void k_qupd(const float* __restrict__ temb, const int* __restrict__ gtime,
                       int s, const float* __restrict__ lw, const float* __restrict__ lb) {
    __shared__ float sq[BB * DD];
    int tid = threadIdx.x;           // 512
    int b = tid >> 6, d = tid & 63;
    int t = gtime[s];
    sq[tid] = g_query[tid] + temb[t * DD + d];
    __syncthreads();
    float acc = lb[d];
    #pragma unroll 8
    for (int k = 0; k < DD; k++) acc = fmaf(sq[b * DD + k], lw[k * DD + d], acc);
    g_query[tid] = acc;
}

// ---------------- sequence build + transformer -------------------------------
__global__ void k_xseq(const int* __restrict__ hp, const float* __restrict__ hte) {
    int row = blockIdx.x;            // 0..B*HL-1
    int b = row / HL;
    int j = threadIdx.x;             // 128
    int p = hp[row];
    float v = (j < DD) ? g_xB[(b * NN + p) * DD + j] : g_query[b * DD + (j - DD)];
    g_xseq[row * DD2 + j] = v + hte[row * DD2 + j];
}

__global__ void k_qkv(const float* __restrict__ Wqkv, int l) {
    __shared__ float sx[DD2];
    int row = blockIdx.x;
    int c = threadIdx.x;             // 384
    if (c < DD2) sx[c] = g_xseq[row * DD2 + c];
    __syncthreads();
    const float* W = Wqkv + l * DD2 * 3 * DD2;
    float acc = 0.f;
    #pragma unroll 8
    for (int k = 0; k < DD2; k++) acc = fmaf(sx[k], __ldg(&W[k * 384 + c]), acc);
    g_qkv[row * 384 + c] = acc;
}

__global__ void k_att() {
    const int PQ = 65;
    __shared__ float sq[HL * PQ];
    __shared__ float sk[HL * PQ];
    __shared__ float sv[HL * PQ];
    __shared__ float ss[HL * HL];
    int b = blockIdx.x, h = blockIdx.y;
    int tid = threadIdx.x;           // 256
    for (int i = tid; i < HL * DD; i += 256) {
        int t = i / DD, d = i & 63;
        int base = (b * HL + t) * 384 + h * 64 + d;
        sq[t * PQ + d] = g_qkv[base];
        sk[t * PQ + d] = g_qkv[base + 128];
        sv[t * PQ + d] = g_qkv[base + 256];
    }
    __syncthreads();
    for (int o = tid; o < HL * HL; o += 256) {
        int i = o / HL, jj = o % HL;
        float acc = 0.f;
        #pragma unroll 8
        for (int d = 0; d < 64; d++) acc = fmaf(sq[i * PQ + d], sk[jj * PQ + d], acc);
        ss[o] = acc * 0.125f;
    }
    __syncthreads();
    for (int i = tid; i < HL; i += 256) {
        float m = -1e30f;
        for (int jj = 0; jj < HL; jj++) m = fmaxf(m, ss[i * HL + jj]);
        float sum = 0.f;
        for (int jj = 0; jj < HL; jj++) { float e = __expf(ss[i * HL + jj] - m); ss[i * HL + jj] = e; sum += e; }
        float inv = 1.f / sum;
        for (int jj = 0; jj < HL; jj++) ss[i * HL + jj] *= inv;
    }
    __syncthreads();
    for (int o = tid; o < HL * DD; o += 256) {
        int i = o / DD, d = o & 63;
        float acc = 0.f;
        #pragma unroll 5
        for (int jj = 0; jj < HL; jj++) acc = fmaf(ss[i * HL + jj], sv[jj * PQ + d], acc);
        g_ao[(b * HL + i) * DD2 + h * 64 + d] = acc;
    }
}

// ---- fused proj + LN1 + FF1 + FF2 + LN2 (one block per row, 128 threads) ----
__global__ void k_ffn(const float* __restrict__ Wo, const float* __restrict__ ln1,
                      const float* __restrict__ W1, const float* __restrict__ b1,
                      const float* __restrict__ W2, const float* __restrict__ b2,
                      const float* __restrict__ ln2, int l) {
    __shared__ float so[DD2];
    __shared__ float xs[DD2];
    __shared__ float sh[512];
    __shared__ float red[DD2];
    int row = blockIdx.x;
    int j = threadIdx.x;             // 128
    so[j] = g_ao[row * DD2 + j];
    __syncthreads();
    // attention out-projection
    const float* W = Wo + l * DD2 * DD2;
    float acc = 0.f;
    #pragma unroll 8
    for (int k = 0; k < DD2; k++) acc = fmaf(so[k], __ldg(&W[k * DD2 + j]), acc);
    float v = g_xseq[row * DD2 + j] + acc;
    // LN1
    red[j] = v;
    __syncthreads();
    for (int off = 64; off > 0; off >>= 1) { if (j < off) red[j] += red[j + off]; __syncthreads(); }
    float mean = red[0] * (1.f / 128.f);
    __syncthreads();
    float dv = v - mean;
    red[j] = dv * dv;
    __syncthreads();
    for (int off = 64; off > 0; off >>= 1) { if (j < off) red[j] += red[j + off]; __syncthreads(); }
    float var = red[0] * (1.f / 128.f);
    __syncthreads();
    const float* ln1l = ln1 + l * 2 * DD2;
    float xv = dv * rsqrtf(var + 1e-5f) * ln1l[j] + ln1l[DD2 + j];
    xs[j] = xv;
    __syncthreads();
    // FF1: 4 contiguous cols per thread, float4 weight loads
    const float* W1l = W1 + l * DD2 * 512;
    float4 a1 = __ldg((const float4*)&b1[l * 512 + j * 4]);
    #pragma unroll 8
    for (int k = 0; k < DD2; k++) {
        float x = xs[k];
        float4 w = __ldg((const float4*)&W1l[k * 512 + j * 4]);
        a1.x = fmaf(x, w.x, a1.x); a1.y = fmaf(x, w.y, a1.y);
        a1.z = fmaf(x, w.z, a1.z); a1.w = fmaf(x, w.w, a1.w);
    }
    float4 r1;
    r1.x = fmaxf(a1.x, 0.f); r1.y = fmaxf(a1.y, 0.f);
    r1.z = fmaxf(a1.z, 0.f); r1.w = fmaxf(a1.w, 0.f);
    *(float4*)&sh[j * 4] = r1;
    __syncthreads();
    // FF2
    const float* W2l = W2 + l * 512 * DD2;
    float a2 = b2[l * DD2 + j];
    #pragma unroll 8
    for (int k = 0; k < 512; k++) a2 = fmaf(sh[k], __ldg(&W2l[k * DD2 + j]), a2);
    float v2 = xs[j] + a2;
    // LN2
    red[j] = v2;
    __syncthreads();
    for (int off = 64; off > 0; off >>= 1) { if (j < off) red[j] += red[j + off]; __syncthreads(); }
    float mean2 = red[0] * (1.f / 128.f);
    __syncthreads();
    float dv2 = v2 - mean2;
    red[j] = dv2 * dv2;
    __syncthreads();
    for (int off = 64; off > 0; off >>= 1) { if (j < off) red[j] += red[j + off]; __syncthreads(); }
    float var2 = red[0] * (1.f / 128.f);
    const float* ln2l = ln2 + l * 2 * DD2;
    g_xseq[row * DD2 + j] = dv2 * rsqrtf(var2 + 1e-5f) * ln2l[j] + ln2l[DD2 + j];
}

__global__ void k_flabel() {
    int b = blockIdx.x;
    int j = threadIdx.x;             // 128
    float s = 0.f;
    for (int t = 0; t < HL; t++) s += g_xseq[(b * HL + t) * DD2 + j];
    g_flabel[b * DD2 + j] = s * (1.f / (float)HL);
}

// ---------------- final scoring MLP -------------------------------------------
__global__ void k_score(const int* __restrict__ tidx,
                        const float* __restrict__ W1, const float* __restrict__ b1,
                        const float* __restrict__ W2, const float* __restrict__ b2,
                        float* __restrict__ out) {
    __shared__ float ft[FDIM];
    __shared__ float sh[256];
    int blk = blockIdx.x;
    int b = blk / KK;
    int j = threadIdx.x;             // 192
    int ti = tidx[blk];
    ft[j] = (j < DD) ? g_xB[(b * NN + ti) * DD + j] : g_flabel[b * DD2 + (j - DD)];
    if (j < 64) sh[192 + j] = 0.f;
    __syncthreads();
    float acc = b1[j];
    #pragma unroll 8
    for (int q = 0; q < FDIM; q++) acc = fmaf(ft[q], __ldg(&W1[q * FDIM + j]), acc);
    float h = fmaxf(acc, 0.f);
    sh[j] = h * W2[j];
    __syncthreads();
    for (int off = 128; off > 0; off >>= 1) { if (j < off) sh[j] += sh[j + off]; __syncthreads(); }
    if (j == 0) out[blk] = sh[0] + b2[0];
}

// ---------------- host launcher -------------------------------------------------
extern "C" void kernel_launch(void* const* d_in, const int* in_sizes, int n_in,
                              void* d_out, int out_size) {
    const float* poi   = (const float*)d_in[0];
    const float* qemb  = (const float*)d_in[1];
    const float* gateW = (const float*)d_in[2];
    const float* gateb = (const float*)d_in[3];
    const float* gnn_rel = (const float*)d_in[4];
    const float* gnn_W   = (const float*)d_in[5];
    const float* gnn_b   = (const float*)d_in[6];
    const float* gte  = (const float*)d_in[7];
    const float* glW  = (const float*)d_in[8];
    const float* glb  = (const float*)d_in[9];
    const float* Wqkv = (const float*)d_in[10];
    const float* Wo   = (const float*)d_in[11];
    const float* ln1  = (const float*)d_in[12];
    const float *W1, *b1, *W2, *b2, *ln2;
    if (in_sizes[13] == 2 * 2 * DD2) {       // dict order: ln2 right after ln1
        ln2 = (const float*)d_in[13];
        W1  = (const float*)d_in[14];
        b1  = (const float*)d_in[15];
        W2  = (const float*)d_in[16];
        b2  = (const float*)d_in[17];
    } else {                                 // signature order
        W1  = (const float*)d_in[13];
        b1  = (const float*)d_in[14];
        W2  = (const float*)d_in[15];
        b2  = (const float*)d_in[16];
        ln2 = (const float*)d_in[17];
    }
    const float* mW1 = (const float*)d_in[18];
    const float* mb1 = (const float*)d_in[19];
    const float* mW2 = (const float*)d_in[20];
    const float* mb2 = (const float*)d_in[21];
    const float* hte = (const float*)d_in[22];
    const int* esrc  = (const int*)d_in[23];
    const int* edst  = (const int*)d_in[24];
    const int* etyp  = (const int*)d_in[25];
    const int* ridx  = (const int*)d_in[27];
    const int* tidx  = (const int*)d_in[28];
    const int* hpoi  = (const int*)d_in[29];
    const int* gtime = (const int*)d_in[30];
    float* out = (float*)d_out;

    k_qinit<<<1, BB * DD>>>(qemb, ridx);

    // batched CSR for all snapshots
    k_zero_counts<<<dim3((NN + 255) / 256, SS), 256>>>();
    k_count<<<dim3((EE + 255) / 256, SS), 256>>>(esrc, edst);
    k_offsets<<<dim3((NN + 255) / 256, SS), 256>>>();
    k_scatter<<<dim3((EE + 255) / 256, SS), 256>>>(esrc, edst, etyp);
    k_relsum<<<dim3(NN * DD / 256, SS), 256>>>(gnn_rel);

    for (int s = 0; s < SS; s++) {
        int nb = (s == 0) ? 1 : BB;          // snapshot 0 is batch-invariant
        if (s == 0)
            k_init0<<<(NN * DD + 255) / 256, 256>>>(poi);
        else
            k_gate_init<<<dim3(NN / 16, BB), 256>>>(poi, gateW, gateb,
                                                    (s == 1) ? 0 : NN * DD, s);
        for (int l = 0; l < 2; l++) {
            k_layer<<<dim3(NN / 16, nb), 512>>>(s, l,
                                                gnn_W + l * 2 * DD * DD,
                                                gnn_b + l * DD);
        }
        k_qupd<<<1, BB * DD>>>(gte, gtime, s, glW, glb);
    }

    k_xseq<<<BB * HL, DD2>>>(hpoi, hte);
    for (int l = 0; l < 2; l++) {
        k_qkv<<<BB * HL, 3 * DD2>>>(Wqkv, l);
        k_att<<<dim3(BB, 2), 256>>>();
        k_ffn<<<BB * HL, DD2>>>(Wo, ln1, W1, b1, W2, b2, ln2, l);
    }
    k_flabel<<<BB, DD2>>>();
    k_score<<<BB * KK, FDIM>>>(tidx, mW1, mb1, mW2, mb2, out);
}